// round 1
// baseline (speedup 1.0000x reference)
#include <cuda_runtime.h>

#define BS  2
#define TT  12
#define B   24        // BS*TT
#define N   150
#define DIN 64
#define F   128       // 2*DIN
#define HH  64
#define NN  (N*N)     // 22500

#define TM  25        // rows per block tile (N/6)
#define TMP 28        // padded row count (multiple of 4, *4B = 112B, 16B-aligned stride)
#define FC  32        // K-chunk for k_ptmp
#define KC  30        // K-chunk for k_final
#define TMA 5         // rows per block for A0/A1

// ---------------- scratch (no allocations allowed) ----------------
__device__ float d_Ptmp[B*NN];
__device__ float d_W[B*NN];
__device__ float d_A0[BS*NN];
__device__ float d_A1[BS*NN];
__device__ float d_g[B*N];
__device__ float d_wg[F];
__device__ float d_cg;
__device__ float d_WfuT[F*N];
__device__ float d_cnt0[BS*N];
__device__ float d_cnt1[BS*N];
__device__ float d_u[BS*N];

// ---------------- K0: fold weights, transpose W_fu ----------------
__global__ void k_prep(const float* __restrict__ WBw, const float* __restrict__ WBb,
                       const float* __restrict__ Wfu, const float* __restrict__ aw) {
    int tid = threadIdx.x;
    if (tid < F) {
        float acc = 0.f;
        #pragma unroll 8
        for (int h = 0; h < HH; h++)
            acc += WBw[h*F + tid] * (aw[h] + aw[h+HH]);
        d_wg[tid] = acc;
    } else if (tid == F) {
        float acc = 0.f;
        for (int h = 0; h < HH; h++) acc += WBb[h] * (aw[h] + aw[h+HH]);
        d_cg = acc;
    }
    for (int idx = tid; idx < F*N; idx += blockDim.x) {
        int f = idx / N, m = idx % N;
        d_WfuT[idx] = Wfu[m*F + f];
    }
}

// ---------------- K1: per-row adjacency counts + column sums ----------------
__global__ void k_cnt(const float* __restrict__ adj) {
    int b = blockIdx.x, tid = threadIdx.x;
    const float* a = adj + b*NN;
    if (tid < N) {
        float c0 = 0.f, c1 = 0.f;
        for (int j = 0; j < 75; j++)  c0 += (a[tid*N + j] > 0.f) ? 1.f : 0.f;
        for (int j = 75; j < N; j++)  c1 += (a[tid*N + j] > 0.f) ? 1.f : 0.f;
        d_cnt0[b*N + tid] = c0;
        d_cnt1[b*N + tid] = c1;
        float u = 0.f;
        for (int i = 0; i < N; i++) u += a[i*N + tid];
        d_u[b*N + tid] = u;
    }
}

// ---------------- K2: A0 = adjL@adj, A1 = adjR@adj (per bs only) ----------------
__global__ __launch_bounds__(160) void k_A(const float* __restrict__ adj) {
    __shared__ float adjS[TMA*N];
    int tile = blockIdx.x, b = blockIdx.y;
    int tid  = threadIdx.x;
    const float* a = adj + b*NN;
    int i0 = tile*TMA;
    for (int idx = tid; idx < TMA*N; idx += blockDim.x)
        adjS[idx] = a[i0*N + idx];
    __syncthreads();
    int n = tid;
    if (n < N) {
        float acc0[TMA] = {}, acc1[TMA] = {};
        for (int j = 0; j < 75; j++) {
            float v = a[j*N + n];
            #pragma unroll
            for (int r = 0; r < TMA; r++) acc0[r] += adjS[r*N + j] * v;
        }
        for (int j = 75; j < N; j++) {
            float v = a[j*N + n];
            #pragma unroll
            for (int r = 0; r < TMA; r++) acc1[r] += adjS[r*N + j] * v;
        }
        #pragma unroll
        for (int r = 0; r < TMA; r++) {
            d_A0[b*NN + (i0+r)*N + n] = acc0[r];
            d_A1[b*NN + (i0+r)*N + n] = acc1[r];
        }
    }
}

// ---------------- K3: P_tmp = ST @ W_fu^T  and  g = ST·w_g + c_g ----------------
__global__ __launch_bounds__(160) void k_ptmp(const float* __restrict__ H,
                                              const float* __restrict__ E) {
    __shared__ __align__(16) float STs[F*TMP];   // [f][r], 14.3 KB
    __shared__ float WfuS[FC*N];                 // 19.2 KB chunk
    int tile = blockIdx.x;   // 0..5
    int bt   = blockIdx.y;   // 0..23
    int tid  = threadIdx.x;
    int i0   = tile*TM;

    for (int idx = tid; idx < TM*F; idx += blockDim.x) {
        int r = idx / F, f = idx % F;
        int row = bt*N + i0 + r;
        float v = (f < DIN) ? H[row*DIN + f] : E[row*DIN + f - DIN];
        STs[f*TMP + r] = v;
    }
    __syncthreads();

    int j = tid;
    float acc[TM] = {};
    for (int f0 = 0; f0 < F; f0 += FC) {
        for (int idx = tid; idx < FC*N; idx += blockDim.x)
            WfuS[idx] = d_WfuT[f0*N + idx];
        __syncthreads();
        if (j < N) {
            #pragma unroll 4
            for (int ff = 0; ff < FC; ff++) {
                float wv = WfuS[ff*N + j];
                const float* st = &STs[(f0+ff)*TMP];
                #pragma unroll
                for (int r4 = 0; r4 < 6; r4++) {
                    float4 s = *(const float4*)(st + r4*4);
                    acc[r4*4+0] += s.x*wv; acc[r4*4+1] += s.y*wv;
                    acc[r4*4+2] += s.z*wv; acc[r4*4+3] += s.w*wv;
                }
                acc[24] += st[24]*wv;
            }
        }
        __syncthreads();
    }
    if (j < N) {
        #pragma unroll
        for (int r = 0; r < TM; r++)
            d_Ptmp[bt*NN + (i0+r)*N + j] = acc[r];
    }
    if (tid < TM) {
        float ga = d_cg;
        #pragma unroll 8
        for (int f = 0; f < F; f++) ga += STs[f*TMP + tid] * d_wg[f];
        d_g[bt*N + i0 + tid] = ga;
    }
}

// ---------------- K4: softmax closed form -> W = diag(p0)A0 + diag(p1)A1 ----------------
__global__ __launch_bounds__(160) void k_W() {
    int bt  = blockIdx.x;
    int b   = bt / TT;
    int tid = threadIdx.x;
    for (int i = 0; i < N; i++) {
        float v0 = d_g[bt*N + (2*i)   % N];
        float v1 = d_g[bt*N + (2*i+1) % N];
        float l0 = v0 > 0.f ? v0 : 0.2f*v0;
        float l1 = v1 > 0.f ? v1 : 0.2f*v1;
        float c0 = d_cnt0[b*N + i], c1 = d_cnt1[b*N + i];
        if (tid < N) {
            float out;
            if (c0 + c1 > 0.f) {
                float mx = fmaxf(l0, l1);
                float e0 = expf(l0 - mx), e1 = expf(l1 - mx);
                float Z  = c0*e0 + c1*e1;
                float p0 = e0 / Z, p1 = e1 / Z;
                out = p0 * d_A0[b*NN + i*N + tid] + p1 * d_A1[b*NN + i*N + tid];
            } else {
                // fully masked row: softmax of all -9e15 is uniform 1/N over ALL j
                out = d_u[b*N + tid] * (1.0f / (float)N);
            }
            d_W[bt*NN + i*N + tid] = out;
        }
    }
}

// ---------------- K5: P = tanh(W @ P_tmp), batched 150x150x150 ----------------
__global__ __launch_bounds__(160) void k_final(float* __restrict__ out) {
    __shared__ __align__(16) float Ws[N*TMP];    // [n][r], 16.8 KB
    __shared__ float Bs[KC*N];                   // 18 KB
    int tile = blockIdx.x, bt = blockIdx.y;
    int tid  = threadIdx.x;
    int i0   = tile*TM;

    for (int idx = tid; idx < TM*N; idx += blockDim.x) {
        int r = idx / N, n = idx % N;
        Ws[n*TMP + r] = d_W[bt*NN + (i0+r)*N + n];
    }
    __syncthreads();

    int j = tid;
    float acc[TM] = {};
    for (int k0 = 0; k0 < N; k0 += KC) {
        for (int idx = tid; idx < KC*N; idx += blockDim.x)
            Bs[idx] = d_Ptmp[bt*NN + k0*N + idx];
        __syncthreads();
        if (j < N) {
            #pragma unroll 5
            for (int kk = 0; kk < KC; kk++) {
                float bv = Bs[kk*N + j];
                const float* wp = &Ws[(k0+kk)*TMP];
                #pragma unroll
                for (int r4 = 0; r4 < 6; r4++) {
                    float4 w = *(const float4*)(wp + r4*4);
                    acc[r4*4+0] += w.x*bv; acc[r4*4+1] += w.y*bv;
                    acc[r4*4+2] += w.z*bv; acc[r4*4+3] += w.w*bv;
                }
                acc[24] += wp[24]*bv;
            }
        }
        __syncthreads();
    }
    if (j < N) {
        #pragma unroll
        for (int r = 0; r < TM; r++)
            out[(bt*N + i0 + r)*N + j] = tanhf(acc[r]);
    }
}

// ---------------- launcher ----------------
extern "C" void kernel_launch(void* const* d_in, const int* in_sizes, int n_in,
                              void* d_out, int out_size) {
    const float* H   = (const float*)d_in[0];
    const float* E   = (const float*)d_in[1];
    const float* adj = (const float*)d_in[2];
    const float* WBw = (const float*)d_in[3];
    const float* WBb = (const float*)d_in[4];
    const float* Wfu = (const float*)d_in[5];
    const float* aw  = (const float*)d_in[6];
    float* out = (float*)d_out;

    k_prep <<<1, 256>>>(WBw, WBb, Wfu, aw);
    k_cnt  <<<BS, 160>>>(adj);
    k_A    <<<dim3(N/TMA, BS), 160>>>(adj);
    k_ptmp <<<dim3(N/TM, B), 160>>>(H, E);
    k_W    <<<B, 160>>>();
    k_final<<<dim3(N/TM, B), 160>>>(out);
}

// round 2
// speedup vs baseline: 2.6537x; 2.6537x over previous
#include <cuda_runtime.h>

#define BS  2
#define TT  12
#define B   24        // BS*TT
#define N   150
#define DIN 64
#define F   128       // 2*DIN
#define HH  64
#define NN  (N*N)     // 22500

#define TM   6        // rows per block tile (150/25)
#define TMP2 8        // padded rows (32B-aligned float4 strides)
#define NTIL 25       // N/TM
#define FC   64       // K-chunk for k_ptmp (2 chunks)
#define KC   50       // K-chunk for k_final (3 chunks)
#define TMA  5        // rows per block for A0/A1

// ---------------- scratch ----------------
__device__ float d_Ptmp[B*NN];
__device__ float d_A0[BS*NN];
__device__ float d_A1[BS*NN];
__device__ float d_g[B*N];
__device__ float d_wg[F];
__device__ float d_cg;
__device__ float d_WfuT[F*N];
__device__ float d_cnt0[BS*N];
__device__ float d_cnt1[BS*N];
__device__ float d_u0[BS*N];
__device__ float d_u1[BS*N];

// ---------------- K0: fold weights + transpose W_fu (8 blocks) ----------------
__global__ void k_prep(const float* __restrict__ WBw, const float* __restrict__ WBb,
                       const float* __restrict__ Wfu, const float* __restrict__ aw) {
    int tid = threadIdx.x;
    if (blockIdx.x == 0) {
        if (tid < F) {
            float acc = 0.f;
            #pragma unroll 8
            for (int h = 0; h < HH; h++)
                acc += WBw[h*F + tid] * (aw[h] + aw[h+HH]);
            d_wg[tid] = acc;
        } else if (tid == F) {
            float acc = 0.f;
            for (int h = 0; h < HH; h++) acc += WBb[h] * (aw[h] + aw[h+HH]);
            d_cg = acc;
        }
    }
    // transpose: coalesced read, scattered write
    int gt = blockIdx.x * blockDim.x + tid;
    for (int idx = gt; idx < N*F; idx += gridDim.x * blockDim.x) {
        int m = idx / F, f = idx % F;
        d_WfuT[f*N + m] = Wfu[idx];
    }
}

// ---------------- K1: A0/A1 halves + row counts + column sums ----------------
__global__ __launch_bounds__(160) void k_A(const float* __restrict__ adj) {
    __shared__ float adjS[TMA*N];
    int tile = blockIdx.x;      // 0..29
    int half = blockIdx.y;      // 0: j<75 -> A0,cnt0,u0 ; 1: j>=75 -> A1,cnt1,u1
    int b    = blockIdx.z;
    int tid  = threadIdx.x;
    const float* a = adj + b*NN;
    int i0 = tile*TMA;
    for (int idx = tid; idx < TMA*N; idx += blockDim.x)
        adjS[idx] = a[i0*N + idx];
    __syncthreads();
    int j0 = half * 75;
    if (tid < TMA) {
        float c = 0.f;
        #pragma unroll 5
        for (int j = j0; j < j0+75; j++) c += (adjS[tid*N + j] > 0.f) ? 1.f : 0.f;
        float* cp = half ? d_cnt1 : d_cnt0;
        cp[b*N + i0 + tid] = c;
    }
    int n = tid;
    if (n < N) {
        float acc[TMA] = {};
        float us = 0.f;
        #pragma unroll 5
        for (int j = j0; j < j0+75; j++) {
            float v = a[j*N + n];
            us += v;
            #pragma unroll
            for (int r = 0; r < TMA; r++) acc[r] += adjS[r*N + j] * v;
        }
        float* A = half ? d_A1 : d_A0;
        #pragma unroll
        for (int r = 0; r < TMA; r++) A[b*NN + (i0+r)*N + n] = acc[r];
        if (tile == 0) {
            float* up = half ? d_u1 : d_u0;
            up[b*N + n] = us;
        }
    }
}

// ---------------- K2: P_tmp = ST @ W_fu^T  and  g = ST·w_g + c_g ----------------
__global__ __launch_bounds__(160) void k_ptmp(const float* __restrict__ H,
                                              const float* __restrict__ E) {
    __shared__ __align__(16) float STs[F*TMP2];   // 4 KB
    __shared__ float WfuS[FC*N];                  // 38.4 KB
    int tile = blockIdx.x;   // 0..24
    int bt   = blockIdx.y;   // 0..23
    int tid  = threadIdx.x;
    int i0   = tile*TM;

    for (int idx = tid; idx < TM*F; idx += blockDim.x) {
        int r = idx / F, f = idx % F;
        int row = bt*N + i0 + r;
        float v = (f < DIN) ? H[row*DIN + f] : E[row*DIN + f - DIN];
        STs[f*TMP2 + r] = v;
    }
    __syncthreads();

    int j = tid;
    float acc[TM] = {};
    for (int f0 = 0; f0 < F; f0 += FC) {
        for (int idx = tid; idx < FC*N; idx += blockDim.x)
            WfuS[idx] = d_WfuT[f0*N + idx];
        __syncthreads();
        if (j < N) {
            #pragma unroll 4
            for (int ff = 0; ff < FC; ff++) {
                float wv = WfuS[ff*N + j];
                const float* st = &STs[(f0+ff)*TMP2];
                float4 s0 = *(const float4*)(st);
                float2 s1 = *(const float2*)(st + 4);
                acc[0] += s0.x*wv; acc[1] += s0.y*wv;
                acc[2] += s0.z*wv; acc[3] += s0.w*wv;
                acc[4] += s1.x*wv; acc[5] += s1.y*wv;
            }
        }
        __syncthreads();
    }
    if (j < N) {
        #pragma unroll
        for (int r = 0; r < TM; r++)
            d_Ptmp[bt*NN + (i0+r)*N + j] = acc[r];
    }
    if (tid < TM) {
        float ga = d_cg;
        #pragma unroll 8
        for (int f = 0; f < F; f++) ga += STs[f*TMP2 + tid] * d_wg[f];
        d_g[bt*N + i0 + tid] = ga;
    }
}

// ---------------- K3: P = tanh((diag(p0)A0 + diag(p1)A1) @ P_tmp) ----------------
__global__ __launch_bounds__(160) void k_final(float* __restrict__ out) {
    __shared__ __align__(16) float Ws[N*TMP2];    // 4.8 KB, [k][r]
    __shared__ float Bs[KC*N];                    // 30 KB
    __shared__ float p0s[TM], p1s[TM];
    __shared__ int   fls[TM];
    int tile = blockIdx.x, bt = blockIdx.y;
    int b    = bt / TT;
    int tid  = threadIdx.x;
    int i0   = tile*TM;

    if (tid < TM) {
        int i = i0 + tid;
        float v0 = d_g[bt*N + (2*i)   % N];
        float v1 = d_g[bt*N + (2*i+1) % N];
        float l0 = v0 > 0.f ? v0 : 0.2f*v0;
        float l1 = v1 > 0.f ? v1 : 0.2f*v1;
        float c0 = d_cnt0[b*N + i], c1 = d_cnt1[b*N + i];
        if (c0 + c1 > 0.f) {
            float mx = fmaxf(l0, l1);
            float e0 = expf(l0 - mx), e1 = expf(l1 - mx);
            float Z  = c0*e0 + c1*e1;
            p0s[tid] = e0 / Z; p1s[tid] = e1 / Z; fls[tid] = 0;
        } else {
            fls[tid] = 1;   // fully-masked row: uniform softmax
        }
    }
    __syncthreads();

    // fused W-tile construction: W[i][k] = p0*A0 + p1*A1  (or colsum/N if masked)
    for (int idx = tid; idx < TM*N; idx += blockDim.x) {
        int r = idx / N, k = idx % N;
        float w;
        if (fls[r]) {
            w = (d_u0[b*N + k] + d_u1[b*N + k]) * (1.0f / (float)N);
        } else {
            w = p0s[r] * d_A0[b*NN + (i0+r)*N + k]
              + p1s[r] * d_A1[b*NN + (i0+r)*N + k];
        }
        Ws[k*TMP2 + r] = w;
    }
    __syncthreads();

    int j = tid;
    float acc[TM] = {};
    for (int k0 = 0; k0 < N; k0 += KC) {
        for (int idx = tid; idx < KC*N; idx += blockDim.x)
            Bs[idx] = d_Ptmp[bt*NN + k0*N + idx];
        __syncthreads();
        if (j < N) {
            #pragma unroll 5
            for (int kk = 0; kk < KC; kk++) {
                float bv = Bs[kk*N + j];
                const float* wp = &Ws[(k0+kk)*TMP2];
                float4 w0 = *(const float4*)(wp);
                float2 w1 = *(const float2*)(wp + 4);
                acc[0] += w0.x*bv; acc[1] += w0.y*bv;
                acc[2] += w0.z*bv; acc[3] += w0.w*bv;
                acc[4] += w1.x*bv; acc[5] += w1.y*bv;
            }
        }
        __syncthreads();
    }
    if (j < N) {
        #pragma unroll
        for (int r = 0; r < TM; r++)
            out[(bt*N + i0 + r)*N + j] = tanhf(acc[r]);
    }
}

// ---------------- launcher ----------------
extern "C" void kernel_launch(void* const* d_in, const int* in_sizes, int n_in,
                              void* d_out, int out_size) {
    const float* H   = (const float*)d_in[0];
    const float* E   = (const float*)d_in[1];
    const float* adj = (const float*)d_in[2];
    const float* WBw = (const float*)d_in[3];
    const float* WBb = (const float*)d_in[4];
    const float* Wfu = (const float*)d_in[5];
    const float* aw  = (const float*)d_in[6];
    float* out = (float*)d_out;

    k_prep <<<8, 256>>>(WBw, WBb, Wfu, aw);
    k_A    <<<dim3(N/TMA, 2, BS), 160>>>(adj);
    k_ptmp <<<dim3(NTIL, B), 160>>>(H, E);
    k_final<<<dim3(NTIL, B), 160>>>(out);
}

// round 3
// speedup vs baseline: 3.1429x; 1.1843x over previous
#include <cuda_runtime.h>

#define BS  2
#define TT  12
#define B   24        // BS*TT
#define N   150
#define DIN 64
#define F   128       // 2*din
#define HH  64
#define NN  (N*N)     // 22500

#define TM   6        // output rows per block tile
#define TMP2 8        // padded row stride (float4-aligned)
#define NTIL 25       // N/TM
#define TMA  3        // rows per A-block
#define ATIL 50       // N/TMA
#define PREB 8        // prep blocks inside k_pre

// ---------------- scratch ----------------
__device__ float d_Ptmp[B*NN];
__device__ float d_A0[BS*NN];
__device__ float d_A1[BS*NN];
__device__ float d_g[B*N];
__device__ float d_wg[F];
__device__ float d_cg;
__device__ float d_WfuT[F*N];
__device__ float d_cnt0[BS*N];
__device__ float d_cnt1[BS*N];
__device__ float d_u0[BS*N];
__device__ float d_u1[BS*N];

// ---------------- K0: weight fold + W_fu transpose + A0/A1/counts/colsums ----------------
__global__ __launch_bounds__(320) void k_pre(const float* __restrict__ adj,
        const float* __restrict__ WBw, const float* __restrict__ WBb,
        const float* __restrict__ Wfu, const float* __restrict__ aw) {
    __shared__ float adjS[TMA*N];
    int bid = blockIdx.x, tid = threadIdx.x;

    if (bid < PREB) {
        if (bid == 0) {
            if (tid < F) {
                float acc = 0.f;
                #pragma unroll 8
                for (int h = 0; h < HH; h++)
                    acc += WBw[h*F + tid] * (aw[h] + aw[h+HH]);
                d_wg[tid] = acc;
            } else if (tid == F) {
                float acc = 0.f;
                for (int h = 0; h < HH; h++) acc += WBb[h] * (aw[h] + aw[h+HH]);
                d_cg = acc;
            }
        }
        for (int idx = bid*320 + tid; idx < N*F; idx += PREB*320) {
            int m = idx / F, f = idx % F;
            d_WfuT[f*N + m] = Wfu[idx];
        }
        return;
    }

    int ab   = bid - PREB;
    int tile = ab % ATIL, b = ab / ATIL;
    const float* a = adj + b*NN;
    int i0 = tile*TMA;
    for (int idx = tid; idx < TMA*N; idx += 320)
        adjS[idx] = a[i0*N + idx];
    __syncthreads();

    int g = tid / 160, n = tid % 160;   // g=0: j<75 (A0), g=1: j>=75 (A1)
    int j0 = g * 75;
    if (n < TMA) {
        float c = 0.f;
        #pragma unroll 5
        for (int j = 0; j < 75; j++)
            c += (adjS[n*N + j0 + j] > 0.f) ? 1.f : 0.f;
        (g ? d_cnt1 : d_cnt0)[b*N + i0 + n] = c;
    }
    if (n < N) {
        float a0 = 0.f, a1 = 0.f, a2 = 0.f, us = 0.f;
        #pragma unroll 5
        for (int j = j0; j < j0 + 75; j++) {
            float v = __ldg(&a[j*N + n]);
            us += v;
            a0 += adjS[0*N + j] * v;
            a1 += adjS[1*N + j] * v;
            a2 += adjS[2*N + j] * v;
        }
        float* A = g ? d_A1 : d_A0;
        A[b*NN + (i0+0)*N + n] = a0;
        A[b*NN + (i0+1)*N + n] = a1;
        A[b*NN + (i0+2)*N + n] = a2;
        if (tile == 0) (g ? d_u1 : d_u0)[b*N + n] = us;
    }
}

// ---------------- K1: P_tmp = ST @ W_fu^T  and  g = ST·w_g + c_g ----------------
// 480 threads = 3 K-split groups of 160; WfuT read straight from L2.
__global__ __launch_bounds__(480) void k_ptmp(const float* __restrict__ H,
                                              const float* __restrict__ E) {
    __shared__ __align__(16) float STs[F*TMP2];   // 4 KB, [f][r]
    __shared__ float red[2*TM*160];               // 7.68 KB
    int tile = blockIdx.x, bt = blockIdx.y, tid = threadIdx.x;
    int i0 = tile*TM;

    for (int idx = tid; idx < TM*F; idx += 480) {
        int r = idx / F, f = idx % F;
        int row = bt*N + i0 + r;
        float v = (f < DIN) ? H[row*DIN + f] : E[row*DIN + f - DIN];
        STs[f*TMP2 + r] = v;
    }
    __syncthreads();

    int g = tid / 160, j = tid % 160;
    int f0 = (g == 0) ? 0 : (g == 1) ? 43 : 86;
    int fl = (g == 2) ? 42 : 43;

    float a0=0.f,a1=0.f,a2=0.f,a3=0.f,a4=0.f,a5=0.f;
    if (j < N) {
        const float* wptr = d_WfuT + f0*N + j;
        const float* st   = STs + f0*TMP2;
        #pragma unroll 4
        for (int ff = 0; ff < fl; ff++) {
            float wv = __ldg(&wptr[ff*N]);
            float4 s0 = *(const float4*)(st + ff*TMP2);
            float2 s1 = *(const float2*)(st + ff*TMP2 + 4);
            a0 += s0.x*wv; a1 += s0.y*wv; a2 += s0.z*wv;
            a3 += s0.w*wv; a4 += s1.x*wv; a5 += s1.y*wv;
        }
    }
    if (g > 0) {
        int base = (g-1)*TM*160 + j;
        red[base + 0*160] = a0; red[base + 1*160] = a1; red[base + 2*160] = a2;
        red[base + 3*160] = a3; red[base + 4*160] = a4; red[base + 5*160] = a5;
    }
    __syncthreads();
    if (g == 0) {
        if (j < N) {
            a0 += red[0*160+j] + red[960 + 0*160+j];
            a1 += red[1*160+j] + red[960 + 1*160+j];
            a2 += red[2*160+j] + red[960 + 2*160+j];
            a3 += red[3*160+j] + red[960 + 3*160+j];
            a4 += red[4*160+j] + red[960 + 4*160+j];
            a5 += red[5*160+j] + red[960 + 5*160+j];
            float* p = d_Ptmp + bt*NN + i0*N + j;
            p[0*N] = a0; p[1*N] = a1; p[2*N] = a2;
            p[3*N] = a3; p[4*N] = a4; p[5*N] = a5;
        }
        if (tid < TM) {
            float ga = d_cg;
            #pragma unroll 8
            for (int f = 0; f < F; f++) ga += STs[f*TMP2 + tid] * d_wg[f];
            d_g[bt*N + i0 + tid] = ga;
        }
    }
}

// ---------------- K2: P = tanh((diag(p0)A0 + diag(p1)A1) @ P_tmp) ----------------
// 480 threads = 3 K-split groups of 160; Ptmp read straight from L2.
__global__ __launch_bounds__(480) void k_final(float* __restrict__ out) {
    __shared__ __align__(16) float Ws[N*TMP2];    // 4.8 KB, [k][r]
    __shared__ float red[2*TM*160];               // 7.68 KB
    __shared__ float p0s[TM], p1s[TM];
    __shared__ int   flm[TM];
    int tile = blockIdx.x, bt = blockIdx.y, b = bt / TT, tid = threadIdx.x;
    int i0 = tile*TM;

    if (tid < TM) {
        int i = i0 + tid;
        float v0 = d_g[bt*N + (2*i)   % N];
        float v1 = d_g[bt*N + (2*i+1) % N];
        float l0 = v0 > 0.f ? v0 : 0.2f*v0;
        float l1 = v1 > 0.f ? v1 : 0.2f*v1;
        float c0 = d_cnt0[b*N + i], c1 = d_cnt1[b*N + i];
        if (c0 + c1 > 0.f) {
            float mx = fmaxf(l0, l1);
            float e0 = expf(l0 - mx), e1 = expf(l1 - mx);
            float Z  = c0*e0 + c1*e1;
            p0s[tid] = e0 / Z; p1s[tid] = e1 / Z; flm[tid] = 0;
        } else {
            flm[tid] = 1;   // fully masked row -> uniform softmax -> colsum/N
        }
    }
    __syncthreads();

    for (int idx = tid; idx < TM*N; idx += 480) {
        int r = idx / N, k = idx % N;
        float w;
        if (flm[r]) {
            w = (d_u0[b*N + k] + d_u1[b*N + k]) * (1.0f / (float)N);
        } else {
            w = p0s[r] * __ldg(&d_A0[b*NN + (i0+r)*N + k])
              + p1s[r] * __ldg(&d_A1[b*NN + (i0+r)*N + k]);
        }
        Ws[k*TMP2 + r] = w;
    }
    __syncthreads();

    int g = tid / 160, j = tid % 160;
    float a0=0.f,a1=0.f,a2=0.f,a3=0.f,a4=0.f,a5=0.f;
    if (j < N) {
        const float* pp = d_Ptmp + bt*NN + g*50*N + j;
        const float* wp = Ws + g*50*TMP2;
        #pragma unroll 5
        for (int k = 0; k < 50; k++) {
            float bv = __ldg(&pp[k*N]);
            float4 w0 = *(const float4*)(wp + k*TMP2);
            float2 w1 = *(const float2*)(wp + k*TMP2 + 4);
            a0 += w0.x*bv; a1 += w0.y*bv; a2 += w0.z*bv;
            a3 += w0.w*bv; a4 += w1.x*bv; a5 += w1.y*bv;
        }
    }
    if (g > 0) {
        int base = (g-1)*TM*160 + j;
        red[base + 0*160] = a0; red[base + 1*160] = a1; red[base + 2*160] = a2;
        red[base + 3*160] = a3; red[base + 4*160] = a4; red[base + 5*160] = a5;
    }
    __syncthreads();
    if (g == 0 && j < N) {
        a0 += red[0*160+j] + red[960 + 0*160+j];
        a1 += red[1*160+j] + red[960 + 1*160+j];
        a2 += red[2*160+j] + red[960 + 2*160+j];
        a3 += red[3*160+j] + red[960 + 3*160+j];
        a4 += red[4*160+j] + red[960 + 4*160+j];
        a5 += red[5*160+j] + red[960 + 5*160+j];
        float* o = out + (bt*N + i0)*N + j;
        o[0*N] = tanhf(a0); o[1*N] = tanhf(a1); o[2*N] = tanhf(a2);
        o[3*N] = tanhf(a3); o[4*N] = tanhf(a4); o[5*N] = tanhf(a5);
    }
}

// ---------------- launcher ----------------
extern "C" void kernel_launch(void* const* d_in, const int* in_sizes, int n_in,
                              void* d_out, int out_size) {
    const float* H   = (const float*)d_in[0];
    const float* E   = (const float*)d_in[1];
    const float* adj = (const float*)d_in[2];
    const float* WBw = (const float*)d_in[3];
    const float* WBb = (const float*)d_in[4];
    const float* Wfu = (const float*)d_in[5];
    const float* aw  = (const float*)d_in[6];
    float* out = (float*)d_out;

    k_pre  <<<PREB + ATIL*BS, 320>>>(adj, WBw, WBb, Wfu, aw);
    k_ptmp <<<dim3(NTIL, B), 480>>>(H, E);
    k_final<<<dim3(NTIL, B), 480>>>(out);
}

// round 4
// speedup vs baseline: 4.1342x; 1.3154x over previous
#include <cuda_runtime.h>

#define BS  2
#define TT  12
#define B   24        // BS*TT
#define N   150
#define DIN 64
#define F   128       // 2*din
#define HH  64
#define NN  (N*N)     // 22500

#define PREB 8        // weight-prep blocks inside k_pre
#define TMA  5        // rows per A-block
#define ATIL 30       // N/TMA
#define RT   15       // output rows per GEMM block tile
#define GTIL 10       // N/RT

// ---------------- scratch ----------------
__device__ float d_Ptmp[B*NN];
__device__ float d_A0[BS*NN];
__device__ float d_A1[BS*NN];
__device__ float d_g[B*N];
__device__ float d_wg[F];
__device__ float d_cg;
__device__ float d_WfuT[F*N];
__device__ float d_cnt0[BS*N];
__device__ float d_cnt1[BS*N];
__device__ float d_u0[BS*N];
__device__ float d_u1[BS*N];

// ==== K0: weight fold + W_fu transpose + A0/A1 + counts + colsums ====
// grid = PREB + ATIL*2*BS = 128 blocks, 480 threads.
__global__ __launch_bounds__(480) void k_pre(const float* __restrict__ adj,
        const float* __restrict__ WBw, const float* __restrict__ WBb,
        const float* __restrict__ Wfu, const float* __restrict__ aw) {
    __shared__ float adjS[TMA*N];            // 3 KB
    __shared__ float red[2*6*160];           // 7.7 KB
    int bid = blockIdx.x, tid = threadIdx.x;

    if (bid < PREB) {
        if (bid == 0) {
            if (tid < F) {
                float acc = 0.f;
                #pragma unroll 8
                for (int h = 0; h < HH; h++)
                    acc += WBw[h*F + tid] * (aw[h] + aw[h+HH]);
                d_wg[tid] = acc;
            } else if (tid == F) {
                float acc = 0.f;
                for (int h = 0; h < HH; h++) acc += WBb[h] * (aw[h] + aw[h+HH]);
                d_cg = acc;
            }
        }
        for (int idx = bid*480 + tid; idx < N*F; idx += PREB*480) {
            int m = idx / F, f = idx % F;
            d_WfuT[f*N + m] = Wfu[idx];
        }
        return;
    }

    int ab   = bid - PREB;
    int tile = ab % ATIL;
    int half = (ab / ATIL) & 1;
    int b    = ab / (2*ATIL);
    const float* a = adj + b*NN;
    int i0 = tile*TMA;

    for (int idx = tid; idx < TMA*N; idx += 480)
        adjS[idx] = a[i0*N + idx];
    __syncthreads();

    int g = tid / 160, n = tid % 160;        // g: j-subgroup of 25
    int j0 = half*75 + g*25;

    // row counts for this half (5 threads of group 0, full 75-j loop over smem)
    if (g == 0 && n < TMA) {
        float c = 0.f;
        int jj0 = half*75;
        #pragma unroll 5
        for (int j = 0; j < 75; j++)
            c += (adjS[n*N + jj0 + j] > 0.f) ? 1.f : 0.f;
        (half ? d_cnt1 : d_cnt0)[b*N + i0 + n] = c;
    }

    float acc[TMA] = {};
    float us = 0.f;
    if (n < N) {
        #pragma unroll 5
        for (int j = j0; j < j0 + 25; j++) {
            float v = __ldg(&a[j*N + n]);
            us += v;
            #pragma unroll
            for (int r = 0; r < TMA; r++) acc[r] += adjS[r*N + j] * v;
        }
    }
    if (g > 0) {
        int base = (g-1)*6*160 + n;
        #pragma unroll
        for (int r = 0; r < TMA; r++) red[base + r*160] = acc[r];
        red[base + 5*160] = us;
    }
    __syncthreads();
    if (g == 0 && n < N) {
        #pragma unroll
        for (int r = 0; r < TMA; r++)
            acc[r] += red[r*160 + n] + red[6*160 + r*160 + n];
        us += red[5*160 + n] + red[6*160 + 5*160 + n];
        float* A = half ? d_A1 : d_A0;
        #pragma unroll
        for (int r = 0; r < TMA; r++)
            A[b*NN + (i0+r)*N + n] = acc[r];
        if (tile == 0) (half ? d_u1 : d_u0)[b*N + n] = us;
    }
}

// ==== K1: P_tmp = ST @ W_fu^T and g = ST·w_g + c_g ====
// block (50,6)=300: tx=col-thread (cols tx,tx+50,tx+100), rg=ty%3 (5 rows), kh=ty/3 (f-half)
__global__ __launch_bounds__(320) void k_ptmp(const float* __restrict__ H,
                                              const float* __restrict__ E) {
    __shared__ __align__(16) float STs[F*16];    // 8 KB, [f][r] stride 16
    __shared__ float red[RT*N];                  // 9 KB
    int tile = blockIdx.x, bt = blockIdx.y;
    int tx = threadIdx.x, tyy = threadIdx.y;
    int rg = tyy % 3, kh = tyy / 3;
    int tid = tyy*50 + tx;
    int i0 = tile*RT;

    for (int idx = tid; idx < RT*F; idx += 300) {
        int r = idx / F, f = idx % F;
        int row = bt*N + i0 + r;
        float v = (f < DIN) ? H[row*DIN + f] : E[row*DIN + f - DIN];
        STs[f*16 + r] = v;
    }
    __syncthreads();

    float acc[5][3] = {};
    int f0 = kh*64;
    const float* wbase = d_WfuT + tx;
    #pragma unroll 4
    for (int ff = 0; ff < 64; ff++) {
        const float* wrow = wbase + (f0+ff)*N;
        float w0 = __ldg(wrow), w1 = __ldg(wrow+50), w2 = __ldg(wrow+100);
        const float* st = STs + (f0+ff)*16 + rg*5;
        #pragma unroll
        for (int u = 0; u < 5; u++) {
            float s = st[u];
            acc[u][0] += s*w0; acc[u][1] += s*w1; acc[u][2] += s*w2;
        }
    }
    if (kh == 1) {
        #pragma unroll
        for (int u = 0; u < 5; u++)
            #pragma unroll
            for (int c = 0; c < 3; c++)
                red[(rg*5+u)*N + c*50 + tx] = acc[u][c];
    }
    __syncthreads();
    if (kh == 0) {
        float* p = d_Ptmp + bt*NN + i0*N;
        #pragma unroll
        for (int u = 0; u < 5; u++)
            #pragma unroll
            for (int c = 0; c < 3; c++)
                p[(rg*5+u)*N + c*50 + tx] =
                    acc[u][c] + red[(rg*5+u)*N + c*50 + tx];
        if (tid < RT) {
            float ga = d_cg;
            #pragma unroll 8
            for (int f = 0; f < F; f++) ga += STs[f*16 + tid] * d_wg[f];
            d_g[bt*N + i0 + tid] = ga;
        }
    }
}

// ==== K2: P = tanh((diag(p0)A0 + diag(p1)A1) @ P_tmp) ====
__global__ __launch_bounds__(320) void k_final(float* __restrict__ out) {
    __shared__ float Ws[N*RT];                   // 9 KB, [k][r] stride 15
    __shared__ float red[RT*N];                  // 9 KB
    __shared__ float p0s[RT], p1s[RT];
    __shared__ int   flm[RT];
    int tile = blockIdx.x, bt = blockIdx.y, b = bt / TT;
    int tx = threadIdx.x, tyy = threadIdx.y;
    int rg = tyy % 3, kh = tyy / 3;
    int tid = tyy*50 + tx;
    int i0 = tile*RT;

    if (tid < RT) {
        int i = i0 + tid;
        float v0 = d_g[bt*N + (2*i)   % N];
        float v1 = d_g[bt*N + (2*i+1) % N];
        float l0 = v0 > 0.f ? v0 : 0.2f*v0;
        float l1 = v1 > 0.f ? v1 : 0.2f*v1;
        float c0 = d_cnt0[b*N + i], c1 = d_cnt1[b*N + i];
        if (c0 + c1 > 0.f) {
            float mx = fmaxf(l0, l1);
            float e0 = expf(l0 - mx), e1 = expf(l1 - mx);
            float Z  = c0*e0 + c1*e1;
            p0s[tid] = e0 / Z; p1s[tid] = e1 / Z; flm[tid] = 0;
        } else {
            flm[tid] = 1;      // fully masked row -> uniform softmax -> colsum/N
        }
    }
    __syncthreads();

    for (int idx = tid; idx < RT*N; idx += 300) {
        int r = idx / N, k = idx % N;
        float w;
        if (flm[r]) {
            w = (d_u0[b*N + k] + d_u1[b*N + k]) * (1.0f / (float)N);
        } else {
            w = p0s[r] * __ldg(&d_A0[b*NN + (i0+r)*N + k])
              + p1s[r] * __ldg(&d_A1[b*NN + (i0+r)*N + k]);
        }
        Ws[k*RT + r] = w;
    }
    __syncthreads();

    float acc[5][3] = {};
    const float* pp = d_Ptmp + bt*NN + kh*75*N + tx;
    const float* wk = Ws + kh*75*RT + rg*5;
    #pragma unroll 5
    for (int kk = 0; kk < 75; kk++) {
        float b0 = __ldg(pp), b1 = __ldg(pp+50), b2 = __ldg(pp+100);
        pp += N;
        #pragma unroll
        for (int u = 0; u < 5; u++) {
            float w = wk[u];
            acc[u][0] += w*b0; acc[u][1] += w*b1; acc[u][2] += w*b2;
        }
        wk += RT;
    }
    if (kh == 1) {
        #pragma unroll
        for (int u = 0; u < 5; u++)
            #pragma unroll
            for (int c = 0; c < 3; c++)
                red[(rg*5+u)*N + c*50 + tx] = acc[u][c];
    }
    __syncthreads();
    if (kh == 0) {
        float* o = out + (bt*N + i0)*N;
        #pragma unroll
        for (int u = 0; u < 5; u++)
            #pragma unroll
            for (int c = 0; c < 3; c++)
                o[(rg*5+u)*N + c*50 + tx] =
                    tanhf(acc[u][c] + red[(rg*5+u)*N + c*50 + tx]);
    }
}

// ---------------- launcher ----------------
extern "C" void kernel_launch(void* const* d_in, const int* in_sizes, int n_in,
                              void* d_out, int out_size) {
    const float* H   = (const float*)d_in[0];
    const float* E   = (const float*)d_in[1];
    const float* adj = (const float*)d_in[2];
    const float* WBw = (const float*)d_in[3];
    const float* WBb = (const float*)d_in[4];
    const float* Wfu = (const float*)d_in[5];
    const float* aw  = (const float*)d_in[6];
    float* out = (float*)d_out;

    dim3 blk(50, 6);
    k_pre  <<<PREB + ATIL*2*BS, 480>>>(adj, WBw, WBb, Wfu, aw);
    k_ptmp <<<dim3(GTIL, B), blk>>>(H, E);
    k_final<<<dim3(GTIL, B), blk>>>(out);
}

// round 5
// speedup vs baseline: 4.2778x; 1.0347x over previous
#include <cuda_runtime.h>

#define BS  2
#define TT  12
#define B   24        // BS*TT
#define N   150
#define DIN 64
#define F   128       // 2*din
#define HH  64
#define NN  (N*N)     // 22500

#define PREB 8        // weight-prep blocks inside k_pre
#define TMA  6        // rows per A-block
#define ATIL 25       // N/TMA
#define JCH  25       // j-chunk staged in smem
#define RT   10       // output rows per GEMM block tile
#define RTS  12       // padded STs row stride
#define GTIL 15       // N/RT

// ---------------- scratch ----------------
__device__ float d_Ptmp[B*NN];
__device__ float d_A0[BS*NN];
__device__ float d_A1[BS*NN];
__device__ float d_g[B*N];
__device__ float d_wg[F];
__device__ float d_cg;
__device__ float d_WfuT[F*N];
__device__ float d_cnt0[BS*N];
__device__ float d_cnt1[BS*N];
__device__ float d_u0[BS*N];
__device__ float d_u1[BS*N];

// ==== K0: weight fold + W_fu transpose + A0/A1 + counts + colsums ====
// grid = PREB + ATIL*2*BS = 108 blocks, 480 threads.
__global__ __launch_bounds__(480) void k_pre(const float* __restrict__ adj,
        const float* __restrict__ WBw, const float* __restrict__ WBb,
        const float* __restrict__ Wfu, const float* __restrict__ aw) {
    __shared__ float adjS[TMA*N];            // 3.6 KB (row operand)
    __shared__ float colS[JCH*N];            // 15 KB  (column operand chunk)
    int bid = blockIdx.x, tid = threadIdx.x;

    if (bid < PREB) {
        if (bid == 0) {
            if (tid < F) {
                float acc = 0.f;
                #pragma unroll 8
                for (int h = 0; h < HH; h++)
                    acc += WBw[h*F + tid] * (aw[h] + aw[h+HH]);
                d_wg[tid] = acc;
            } else if (tid == F) {
                float acc = 0.f;
                for (int h = 0; h < HH; h++) acc += WBb[h] * (aw[h] + aw[h+HH]);
                d_cg = acc;
            }
        }
        for (int idx = bid*480 + tid; idx < N*F; idx += PREB*480) {
            int m = idx / F, f = idx % F;
            d_WfuT[f*N + m] = Wfu[idx];
        }
        return;
    }

    int ab   = bid - PREB;
    int tile = ab % ATIL;
    int half = (ab / ATIL) & 1;
    int b    = ab / (2*ATIL);
    const float* a = adj + b*NN;
    int i0 = tile*TMA;
    int j0 = half*75;

    for (int idx = tid; idx < TMA*N; idx += 480)
        adjS[idx] = a[i0*N + idx];
    __syncthreads();

    // row counts for this tile's 6 rows over the half's j-range
    if (tid < TMA) {
        float c = 0.f;
        #pragma unroll 5
        for (int j = 0; j < 75; j++)
            c += (adjS[tid*N + j0 + j] > 0.f) ? 1.f : 0.f;
        (half ? d_cnt1 : d_cnt0)[b*N + i0 + tid] = c;
    }

    int g = tid / 160, n = tid % 160;        // g: 2-row group (rows g*2, g*2+1)
    int r0 = g*2;
    float acc0 = 0.f, acc1 = 0.f, us = 0.f;

    for (int c = 0; c < 3; c++) {
        __syncthreads();
        // bulk-stage rows [j0+c*25, j0+c*25+25) of adj: 3750 contiguous floats
        const float* src = a + (j0 + c*JCH)*N;
        for (int idx = tid; idx < JCH*N; idx += 480)
            colS[idx] = src[idx];
        __syncthreads();
        if (n < N) {
            int jb = j0 + c*JCH;
            #pragma unroll 5
            for (int jj = 0; jj < JCH; jj++) {
                float v = colS[jj*N + n];
                us   += v;
                acc0 += adjS[r0*N + jb + jj] * v;
                acc1 += adjS[(r0+1)*N + jb + jj] * v;
            }
        }
    }
    if (n < N) {
        float* A = half ? d_A1 : d_A0;
        A[b*NN + (i0+r0)*N + n]   = acc0;
        A[b*NN + (i0+r0+1)*N + n] = acc1;
        if (g == 0 && tile == 0) (half ? d_u1 : d_u0)[b*N + n] = us;
    }
}

// ==== K1: P_tmp = ST @ W_fu^T and g = ST·w_g + c_g ====
// block (50,6)=300: tx -> cols {tx, tx+50, tx+100}; rg=ty%2 -> 5 rows; kh=ty/2 -> f-split
__global__ __launch_bounds__(320) void k_ptmp(const float* __restrict__ H,
                                              const float* __restrict__ E) {
    __shared__ __align__(16) float STs[F*RTS];   // 6.1 KB, [f][r]
    __shared__ float red[2*RT*N];                // 12 KB
    int tile = blockIdx.x, bt = blockIdx.y;
    int tx = threadIdx.x, tyy = threadIdx.y;
    int rg = tyy % 2, kh = tyy / 2;
    int tid = tyy*50 + tx;
    int i0 = tile*RT;

    for (int idx = tid; idx < RT*F; idx += 300) {
        int r = idx / F, f = idx % F;
        int row = bt*N + i0 + r;
        float v = (f < DIN) ? H[row*DIN + f] : E[row*DIN + f - DIN];
        STs[f*RTS + r] = v;
    }
    __syncthreads();

    float acc[5][3] = {};
    int f0 = (kh == 0) ? 0 : (kh == 1) ? 43 : 86;
    int fl = (kh == 2) ? 42 : 43;
    const float* wbase = d_WfuT + tx;
    #pragma unroll 4
    for (int ff = 0; ff < fl; ff++) {
        const float* wrow = wbase + (f0+ff)*N;
        float w0 = __ldg(wrow), w1 = __ldg(wrow+50), w2 = __ldg(wrow+100);
        const float* st = STs + (f0+ff)*RTS + rg*5;
        #pragma unroll
        for (int u = 0; u < 5; u++) {
            float s = st[u];
            acc[u][0] += s*w0; acc[u][1] += s*w1; acc[u][2] += s*w2;
        }
    }
    if (kh > 0) {
        float* rd = red + (kh-1)*RT*N;
        #pragma unroll
        for (int u = 0; u < 5; u++)
            #pragma unroll
            for (int c = 0; c < 3; c++)
                rd[(rg*5+u)*N + c*50 + tx] = acc[u][c];
    }
    __syncthreads();
    if (kh == 0) {
        float* p = d_Ptmp + bt*NN + i0*N;
        #pragma unroll
        for (int u = 0; u < 5; u++)
            #pragma unroll
            for (int c = 0; c < 3; c++) {
                int off = (rg*5+u)*N + c*50 + tx;
                p[off] = acc[u][c] + red[off] + red[RT*N + off];
            }
        if (tid < RT) {
            float ga = d_cg;
            #pragma unroll 8
            for (int f = 0; f < F; f++) ga += STs[f*RTS + tid] * d_wg[f];
            d_g[bt*N + i0 + tid] = ga;
        }
    }
}

// ==== K2: P = tanh((diag(p0)A0 + diag(p1)A1) @ P_tmp) ====
__global__ __launch_bounds__(320) void k_final(float* __restrict__ out) {
    __shared__ float Ws[N*RT];                   // 6 KB, [k][r]
    __shared__ float red[2*RT*N];                // 12 KB
    __shared__ float p0s[RT], p1s[RT];
    __shared__ int   flm[RT];
    int tile = blockIdx.x, bt = blockIdx.y, b = bt / TT;
    int tx = threadIdx.x, tyy = threadIdx.y;
    int rg = tyy % 2, kh = tyy / 2;
    int tid = tyy*50 + tx;
    int i0 = tile*RT;

    if (tid < RT) {
        int i = i0 + tid;
        float v0 = d_g[bt*N + (2*i)   % N];
        float v1 = d_g[bt*N + (2*i+1) % N];
        float l0 = v0 > 0.f ? v0 : 0.2f*v0;
        float l1 = v1 > 0.f ? v1 : 0.2f*v1;
        float c0 = d_cnt0[b*N + i], c1 = d_cnt1[b*N + i];
        if (c0 + c1 > 0.f) {
            float mx = fmaxf(l0, l1);
            float e0 = expf(l0 - mx), e1 = expf(l1 - mx);
            float Z  = c0*e0 + c1*e1;
            p0s[tid] = e0 / Z; p1s[tid] = e1 / Z; flm[tid] = 0;
        } else {
            flm[tid] = 1;      // fully masked row -> uniform softmax -> colsum/N
        }
    }
    __syncthreads();

    for (int idx = tid; idx < RT*N; idx += 300) {
        int r = idx / N, k = idx % N;
        float w;
        if (flm[r]) {
            w = (d_u0[b*N + k] + d_u1[b*N + k]) * (1.0f / (float)N);
        } else {
            w = p0s[r] * __ldg(&d_A0[b*NN + (i0+r)*N + k])
              + p1s[r] * __ldg(&d_A1[b*NN + (i0+r)*N + k]);
        }
        Ws[k*RT + r] = w;
    }
    __syncthreads();

    float acc[5][3] = {};
    const float* pp = d_Ptmp + bt*NN + kh*50*N + tx;
    const float* wk = Ws + kh*50*RT + rg*5;
    #pragma unroll 5
    for (int kk = 0; kk < 50; kk++) {
        float b0 = __ldg(pp), b1 = __ldg(pp+50), b2 = __ldg(pp+100);
        pp += N;
        #pragma unroll
        for (int u = 0; u < 5; u++) {
            float w = wk[u];
            acc[u][0] += w*b0; acc[u][1] += w*b1; acc[u][2] += w*b2;
        }
        wk += RT;
    }
    if (kh > 0) {
        float* rd = red + (kh-1)*RT*N;
        #pragma unroll
        for (int u = 0; u < 5; u++)
            #pragma unroll
            for (int c = 0; c < 3; c++)
                rd[(rg*5+u)*N + c*50 + tx] = acc[u][c];
    }
    __syncthreads();
    if (kh == 0) {
        float* o = out + (bt*N + i0)*N;
        #pragma unroll
        for (int u = 0; u < 5; u++)
            #pragma unroll
            for (int c = 0; c < 3; c++) {
                int off = (rg*5+u)*N + c*50 + tx;
                o[off] = tanhf(acc[u][c] + red[off] + red[RT*N + off]);
            }
    }
}

// ---------------- launcher ----------------
extern "C" void kernel_launch(void* const* d_in, const int* in_sizes, int n_in,
                              void* d_out, int out_size) {
    const float* H   = (const float*)d_in[0];
    const float* E   = (const float*)d_in[1];
    const float* adj = (const float*)d_in[2];
    const float* WBw = (const float*)d_in[3];
    const float* WBb = (const float*)d_in[4];
    const float* Wfu = (const float*)d_in[5];
    const float* aw  = (const float*)d_in[6];
    float* out = (float*)d_out;

    dim3 blk(50, 6);
    k_pre  <<<PREB + ATIL*2*BS, 480>>>(adj, WBw, WBb, Wfu, aw);
    k_ptmp <<<dim3(GTIL, B), blk>>>(H, E);
    k_final<<<dim3(GTIL, B), blk>>>(out);
}